// round 8
// baseline (speedup 1.0000x reference)
#include <cuda_runtime.h>
#include <cuda_bf16.h>
#include <cstddef>
#include <cstdint>

// ---------------------------------------------------------------------------
// TransNet, mma.sync bf16 split-precision GEMM, 3 CTA/SM + fused rhs epilogue.
//   Layer solve:  v·(cI + dt^2 W^T W) = rhs_v + dt·rhs_u@W
//   u_out = -u = dt·v@W^T - rhs_u,  v_out = -v
//   (cI + dt^2 K)^{-1} ≈ (1/c)(I - aK)   [first-order Neumann, err ~1.5e-6]
// GEMMs NT: C[m,n] = sum_k A[m,k]*B[n,k] as AhBh + AlBh + AhBl (fp32 accum).
// BK=32, 3-stage cp.async, warp tile 32x32, rhs-mode epilogue builds next
// layer's (Ru fp32+splits, Rv fp32) in-place.
// ---------------------------------------------------------------------------

#define BATCH   8192
#define UNITS   1024
#define INDIM   2048
#define OUTDIM  1000

static const float DT     = 0.1f;
static const float CCONST = 11.0f;           // 1 + dt/eps
static const float ACONST = 0.01f / 11.0f;   // dt^2 / c

// ------------------------------- scratch (16B+ aligned) --------------------
__device__ __align__(256) float g_b0[BATCH * UNITS];
__device__ __align__(256) float g_b1[BATCH * UNITS];
__device__ __align__(256) float g_b2[BATCH * UNITS];
__device__ __align__(256) float g_b3[BATCH * UNITS];
__device__ __align__(256) float g_s1[UNITS * UNITS];   // K fp32

__device__ __align__(256) unsigned short g_xh[BATCH * INDIM];
__device__ __align__(256) unsigned short g_xl[BATCH * INDIM];
__device__ __align__(256) unsigned short g_winh[UNITS * INDIM];
__device__ __align__(256) unsigned short g_winl[UNITS * INDIM];
__device__ __align__(256) unsigned short g_hah[BATCH * UNITS];
__device__ __align__(256) unsigned short g_hal[BATCH * UNITS];
__device__ __align__(256) unsigned short g_hbh[BATCH * UNITS];
__device__ __align__(256) unsigned short g_hbl[BATCH * UNITS];
__device__ __align__(256) unsigned short g_wh[UNITS * UNITS];
__device__ __align__(256) unsigned short g_wl[UNITS * UNITS];
__device__ __align__(256) unsigned short g_s0h[UNITS * UNITS];
__device__ __align__(256) unsigned short g_s0l[UNITS * UNITS];
__device__ __align__(256) unsigned short g_mih[UNITS * UNITS];
__device__ __align__(256) unsigned short g_mil[UNITS * UNITS];
__device__ __align__(256) unsigned short g_woh[OUTDIM * UNITS];
__device__ __align__(256) unsigned short g_wol[OUTDIM * UNITS];

// ------------------------------ helpers ------------------------------------
__device__ __forceinline__ uint32_t smem_u32(const void* p) {
    uint32_t a;
    asm("{ .reg .u64 t; cvta.to.shared.u64 t, %1; cvt.u32.u64 %0, t; }"
        : "=r"(a) : "l"(p));
    return a;
}

// cp.async 16B global->shared; src_sz=0 zero-fills (OOB rows)
__device__ __forceinline__ void cp16(uint32_t dst, const void* src, bool inb) {
    int sz = inb ? 16 : 0;
    asm volatile(
        "{\n\t.reg .u64 g;\n\tcvta.to.global.u64 g, %1;\n\t"
        "cp.async.cg.shared.global [%0], [g], 16, %2;\n\t}"
        :: "r"(dst), "l"(src), "r"(sz) : "memory");
}
__device__ __forceinline__ void cp_commit() {
    asm volatile("cp.async.commit_group;" ::: "memory");
}
__device__ __forceinline__ void cp_wait1() {
    asm volatile("cp.async.wait_group 1;" ::: "memory");
}

// mma.sync m16n8k16 row.col f32 <- bf16 x bf16 + f32
__device__ __forceinline__ void mma16816(float* d, const uint32_t* a, const uint32_t* b) {
    asm volatile(
        "mma.sync.aligned.m16n8k16.row.col.f32.bf16.bf16.f32 "
        "{%0,%1,%2,%3}, {%4,%5,%6,%7}, {%8,%9}, {%0,%1,%2,%3};"
        : "+f"(d[0]), "+f"(d[1]), "+f"(d[2]), "+f"(d[3])
        : "r"(a[0]), "r"(a[1]), "r"(a[2]), "r"(a[3]), "r"(b[0]), "r"(b[1]));
}

// ldmatrix x4: four 8x8 b16 matrices
__device__ __forceinline__ void ldsm4(uint32_t* r, uint32_t addr) {
    asm volatile("ldmatrix.sync.aligned.m8n8.x4.shared.b16 {%0,%1,%2,%3}, [%4];"
        : "=r"(r[0]), "=r"(r[1]), "=r"(r[2]), "=r"(r[3]) : "r"(addr));
}

__device__ __forceinline__ void split1(float x, unsigned short& h, unsigned short& l) {
    __nv_bfloat16 hb = __float2bfloat16(x);
    h = __bfloat16_as_ushort(hb);
    l = __bfloat16_as_ushort(__float2bfloat16(x - __bfloat162float(hb)));
}

// --------------------------- GEMM kernel -----------------------------------
// d[m,n] = alpha*sum_k A[m,k]B[n,k] (+bias[n]) (+add_scale*addp[m,n]) (+diag)
// Plain mode (bias2==null): C=d fp32, Crelu=relu(d), (Ch,Cl)=split(d).
// rhs mode (bias2!=null):   Ru = d + 0.1*bias2[n]; C=Ru, (Ch,Cl)=split(Ru);
//                           Rv = 10*relu(d) + (vprev? svv*vprev : relu(d));
//                           Crelu = Rv.
// Tiles: BM=128, BN=64, BK=32. Rows 64B; swizzle chunk ^= (row>>1)&3.
#define BM 128
#define BN 64
#define BK 32
#define A_TILE_B (128 * 64)
#define B_TILE_B (64 * 64)
#define STAGE_B  (2 * A_TILE_B + 2 * B_TILE_B)  // 24576
#define NSTAGE 3
#define SMEM_GEMM (1024 + NSTAGE * STAGE_B)     // 74752

__global__ __launch_bounds__(256, 3) void gemm_tc(
    const unsigned short* __restrict__ Ah, const unsigned short* __restrict__ Al,
    const unsigned short* __restrict__ Bh, const unsigned short* __restrict__ Bl,
    float* __restrict__ C, float* __restrict__ Crelu,
    unsigned short* __restrict__ Ch, unsigned short* __restrict__ Cl,
    int M, int N, int K, float alpha,
    const float* __restrict__ bias, float diag_add,
    const float* __restrict__ addp, float add_scale,
    const float* __restrict__ bias2, const float* __restrict__ vprev, float svv)
{
    extern __shared__ char smem[];
    const uint32_t sbase = smem_u32(smem) + 1024;
    const int tid  = threadIdx.x;
    const int wid  = tid >> 5;
    const int lane = tid & 31;
    const int bm = blockIdx.y * BM;
    const int bn = blockIdx.x * BN;
    const int nc = K / BK;

    auto issue_stage = [&](int c) {
        const int k0 = c * BK;
        const uint32_t sd = sbase + (c % NSTAGE) * STAGE_B;
#pragma unroll
        for (int t = 0; t < 2; ++t) {
            const unsigned short* src = t ? Al : Ah;
            const uint32_t tb = sd + t * A_TILE_B;
#pragma unroll
            for (int p = 0; p < 2; ++p) {
                int s   = tid + p * 256;
                int row = s >> 2, ch = s & 3;
                uint32_t addr = tb + (uint32_t)row * 64u
                              + (uint32_t)((ch ^ ((row >> 1) & 3)) << 4);
                cp16(addr, src + (size_t)(bm + row) * K + k0 + ch * 8,
                     bm + row < M);
            }
        }
#pragma unroll
        for (int t = 0; t < 2; ++t) {
            const unsigned short* src = t ? Bl : Bh;
            const uint32_t tb = sd + 2 * A_TILE_B + t * B_TILE_B;
            int row = tid >> 2, ch = tid & 3;
            uint32_t addr = tb + (uint32_t)row * 64u
                          + (uint32_t)((ch ^ ((row >> 1) & 3)) << 4);
            cp16(addr, src + (size_t)(bn + row) * K + k0 + ch * 8,
                 bn + row < N);
        }
        cp_commit();
    };

    // warp tiling: warp (wm, wn) owns rows [wm*32,+32) x cols [wn*32,+32)
    const int wm = wid & 3;
    const int wn = wid >> 2;
    const int r  = lane >> 2;
    const int c2 = (lane & 3) * 2;

    const int q    = lane >> 3;
    const int rin  = lane & 7;
    const int rsw  = rin >> 1;
    const uint32_t a_row = (uint32_t)(wm * 32 + (q & 1) * 8 + rin) * 64u;
    const int a_sel = q >> 1;
    const uint32_t b_row = (uint32_t)(wn * 32 + (q >> 1) * 8 + rin) * 64u;
    const int b_sel = q & 1;

    float acc[2][4][4];
#pragma unroll
    for (int a = 0; a < 2; ++a)
#pragma unroll
        for (int b = 0; b < 4; ++b)
#pragma unroll
            for (int k = 0; k < 4; ++k) acc[a][b][k] = 0.0f;

    issue_stage(0);
    if (nc > 1) issue_stage(1);

    for (int c = 0; c < nc; ++c) {
        cp_wait1();
        __syncthreads();
        if (c + 2 < nc) issue_stage(c + 2);

        const uint32_t tAh = sbase + (c % NSTAGE) * STAGE_B;
        const uint32_t tAl = tAh + A_TILE_B;
        const uint32_t tBh = tAh + 2 * A_TILE_B;
        const uint32_t tBl = tBh + B_TILE_B;

#pragma unroll
        for (int ks = 0; ks < 2; ++ks) {
            const uint32_t aoff = (uint32_t)(((ks * 2 + a_sel) ^ rsw)) << 4;
            const uint32_t boff = (uint32_t)(((ks * 2 + b_sel) ^ rsw)) << 4;

            uint32_t ah[2][4], al[2][4];
            ldsm4(ah[0], tAh + a_row + aoff);
            ldsm4(ah[1], tAh + a_row + 1024u + aoff);
            ldsm4(al[0], tAl + a_row + aoff);
            ldsm4(al[1], tAl + a_row + 1024u + aoff);

            uint32_t bh[4][2], bl[4][2];
#pragma unroll
            for (int p = 0; p < 2; ++p) {
                uint32_t r4[4];
                ldsm4(r4, tBh + b_row + (uint32_t)p * 1024u + boff);
                bh[2 * p][0] = r4[0]; bh[2 * p][1] = r4[1];
                bh[2 * p + 1][0] = r4[2]; bh[2 * p + 1][1] = r4[3];
                ldsm4(r4, tBl + b_row + (uint32_t)p * 1024u + boff);
                bl[2 * p][0] = r4[0]; bl[2 * p][1] = r4[1];
                bl[2 * p + 1][0] = r4[2]; bl[2 * p + 1][1] = r4[3];
            }

#pragma unroll
            for (int nt = 0; nt < 4; ++nt) {
                mma16816(acc[0][nt], ah[0], bh[nt]);
                mma16816(acc[1][nt], ah[1], bh[nt]);
            }
#pragma unroll
            for (int nt = 0; nt < 4; ++nt) {
                mma16816(acc[0][nt], al[0], bh[nt]);
                mma16816(acc[1][nt], al[1], bh[nt]);
            }
#pragma unroll
            for (int nt = 0; nt < 4; ++nt) {
                mma16816(acc[0][nt], ah[0], bl[nt]);
                mma16816(acc[1][nt], ah[1], bl[nt]);
            }
        }
    }
    __syncthreads();

    // epilogue
#pragma unroll
    for (int mt = 0; mt < 2; ++mt) {
#pragma unroll
        for (int nt = 0; nt < 4; ++nt) {
            const int col = bn + wn * 32 + nt * 8 + c2;
            if (col >= N) continue;
            float bx = 0.f, by = 0.f;
            if (bias) { bx = bias[col]; by = bias[col + 1]; }
#pragma unroll
            for (int h = 0; h < 2; ++h) {
                const int m = bm + wm * 32 + mt * 16 + r + h * 8;
                float d0 = alpha * acc[mt][nt][2 * h + 0] + bx;
                float d1 = alpha * acc[mt][nt][2 * h + 1] + by;
                size_t idx = (size_t)m * N + col;
                if (addp) {
                    d0 += add_scale * addp[idx];
                    d1 += add_scale * addp[idx + 1];
                }
                if (diag_add != 0.0f) {
                    if (m == col)     d0 += diag_add;
                    if (m == col + 1) d1 += diag_add;
                }
                if (bias2) {
                    // rhs mode: Rv then Ru (d becomes Ru)
                    float r0 = fmaxf(d0, 0.f), r1 = fmaxf(d1, 0.f);
                    float rv0 = 10.f * r0, rv1 = 10.f * r1;
                    if (vprev) {
                        float2 vp = *(const float2*)(vprev + idx);
                        rv0 += svv * vp.x; rv1 += svv * vp.y;
                    } else {
                        rv0 += r0; rv1 += r1;
                    }
                    *(float2*)(Crelu + idx) = make_float2(rv0, rv1);
                    d0 += 0.1f * bias2[col];
                    d1 += 0.1f * bias2[col + 1];
                } else if (Crelu) {
                    *(float2*)(Crelu + idx) =
                        make_float2(fmaxf(d0, 0.f), fmaxf(d1, 0.f));
                }
                if (C) *(float2*)(C + idx) = make_float2(d0, d1);
                if (Ch) {
                    unsigned short h0, l0, h1, l1;
                    split1(d0, h0, l0);
                    split1(d1, h1, l1);
                    *(ushort2*)(Ch + idx) = make_ushort2(h0, h1);
                    *(ushort2*)(Cl + idx) = make_ushort2(l0, l1);
                }
            }
        }
    }
}

// ----------------------------- elementwise ---------------------------------
__global__ void split_hl(const float* __restrict__ src,
                         unsigned short* __restrict__ h,
                         unsigned short* __restrict__ l, int n)
{
    int i = blockIdx.x * blockDim.x + threadIdx.x;
    if (i * 4 < n) {
        float4 v = *(const float4*)(src + i * 4);
        ushort4 hs, ls;
        split1(v.x, hs.x, ls.x); split1(v.y, hs.y, ls.y);
        split1(v.z, hs.z, ls.z); split1(v.w, hs.w, ls.w);
        *(ushort4*)(h + i * 4) = hs;
        *(ushort4*)(l + i * 4) = ls;
    }
}

// one pass over W: direct split -> (wh, wl); transposed split -> (th, tl)
__global__ void weight_split_both(unsigned short* __restrict__ wh,
                                  unsigned short* __restrict__ wl,
                                  unsigned short* __restrict__ th,
                                  unsigned short* __restrict__ tl,
                                  const float* __restrict__ W, int n)
{
    __shared__ float t[32][33];
    int x = blockIdx.x * 32 + threadIdx.x;
    int y = blockIdx.y * 32 + threadIdx.y;
    float v = W[(size_t)y * n + x];
    t[threadIdx.y][threadIdx.x] = v;
    unsigned short h, l;
    split1(v, h, l);
    wh[(size_t)y * n + x] = h;
    wl[(size_t)y * n + x] = l;
    __syncthreads();
    int ox = blockIdx.y * 32 + threadIdx.x;
    int oy = blockIdx.x * 32 + threadIdx.y;
    split1(t[threadIdx.x][threadIdx.y], h, l);
    th[(size_t)oy * n + ox] = h;
    tl[(size_t)oy * n + ox] = l;
}

// dst = scale*src + diag*I, emitted as hi/lo bf16
__global__ void scale_diag_split(unsigned short* __restrict__ dh,
                                 unsigned short* __restrict__ dl,
                                 const float* __restrict__ src,
                                 float scale, float diag, int dim)
{
    int i = blockIdx.x * blockDim.x + threadIdx.x;
    if (i < dim * dim) {
        float v = scale * src[i];
        if ((i / dim) == (i % dim)) v += diag;
        unsigned short h, l;
        split1(v, h, l);
        dh[i] = h; dl[i] = l;
    }
}

__global__ void softmax_rows(float* __restrict__ data, int cols)
{
    int row = blockIdx.x;
    float* d = data + (size_t)row * cols;
    __shared__ float sm[32];
    int tid = threadIdx.x, lane = tid & 31, warp = tid >> 5;
    int nwarp = blockDim.x >> 5;

    float m = -3.4e38f;
    for (int i = tid; i < cols; i += blockDim.x) m = fmaxf(m, d[i]);
#pragma unroll
    for (int o = 16; o; o >>= 1) m = fmaxf(m, __shfl_xor_sync(0xffffffffu, m, o));
    if (lane == 0) sm[warp] = m;
    __syncthreads();
    if (warp == 0) {
        float t = (lane < nwarp) ? sm[lane] : -3.4e38f;
#pragma unroll
        for (int o = 16; o; o >>= 1) t = fmaxf(t, __shfl_xor_sync(0xffffffffu, t, o));
        if (lane == 0) sm[0] = t;
    }
    __syncthreads();
    float mx = sm[0];
    __syncthreads();

    float s = 0.0f;
    for (int i = tid; i < cols; i += blockDim.x) {
        float e = expf(d[i] - mx);
        d[i] = e;
        s += e;
    }
#pragma unroll
    for (int o = 16; o; o >>= 1) s += __shfl_xor_sync(0xffffffffu, s, o);
    if (lane == 0) sm[warp] = s;
    __syncthreads();
    if (warp == 0) {
        float t = (lane < nwarp) ? sm[lane] : 0.0f;
#pragma unroll
        for (int o = 16; o; o >>= 1) t += __shfl_xor_sync(0xffffffffu, t, o);
        if (lane == 0) sm[0] = t;
    }
    __syncthreads();
    float inv = 1.0f / sm[0];
    for (int i = tid; i < cols; i += blockDim.x) d[i] *= inv;
}

// ---------------------------------------------------------------------------
extern "C" void kernel_launch(void* const* d_in, const int* in_sizes, int n_in,
                              void* d_out, int out_size)
{
    const float* x     = (const float*)d_in[0];
    const float* W_in  = (const float*)d_in[1];
    const float* b_in  = (const float*)d_in[2];
    const float* Ws[3] = {(const float*)d_in[3], (const float*)d_in[5], (const float*)d_in[7]};
    const float* bs[3] = {(const float*)d_in[4], (const float*)d_in[6], (const float*)d_in[8]};
    const float* W_out = (const float*)d_in[9];
    const float* b_out = (const float*)d_in[10];
    float* out = (float*)d_out;

    cudaFuncSetAttribute(gemm_tc, cudaFuncAttributeMaxDynamicSharedMemorySize, SMEM_GEMM);

    float *b0, *b1, *b2, *b3, *s1;
    cudaGetSymbolAddress((void**)&b0, g_b0);
    cudaGetSymbolAddress((void**)&b1, g_b1);
    cudaGetSymbolAddress((void**)&b2, g_b2);
    cudaGetSymbolAddress((void**)&b3, g_b3);
    cudaGetSymbolAddress((void**)&s1, g_s1);
    unsigned short *xh, *xl, *winh, *winl;
    unsigned short *P0h, *P0l, *P1h, *P1l;
    unsigned short *wh, *wl, *s0h, *s0l, *mih, *mil, *woh, *wol;
    cudaGetSymbolAddress((void**)&xh, g_xh);   cudaGetSymbolAddress((void**)&xl, g_xl);
    cudaGetSymbolAddress((void**)&winh, g_winh); cudaGetSymbolAddress((void**)&winl, g_winl);
    cudaGetSymbolAddress((void**)&P0h, g_hah); cudaGetSymbolAddress((void**)&P0l, g_hal);
    cudaGetSymbolAddress((void**)&P1h, g_hbh); cudaGetSymbolAddress((void**)&P1l, g_hbl);
    cudaGetSymbolAddress((void**)&wh, g_wh);   cudaGetSymbolAddress((void**)&wl, g_wl);
    cudaGetSymbolAddress((void**)&s0h, g_s0h); cudaGetSymbolAddress((void**)&s0l, g_s0l);
    cudaGetSymbolAddress((void**)&mih, g_mih); cudaGetSymbolAddress((void**)&mil, g_mil);
    cudaGetSymbolAddress((void**)&woh, g_woh); cudaGetSymbolAddress((void**)&wol, g_wol);

    dim3 gBig(UNITS / BN, BATCH / BM);                 // (16, 64)
    dim3 gSmall(UNITS / BN, UNITS / BM);               // (16, 8)
    dim3 gOut((OUTDIM + BN - 1) / BN, BATCH / BM);     // (16, 64)
    dim3 tblk(32, 32), tgrid(UNITS / 32, UNITS / 32);
    int sdBlocks = (UNITS * UNITS + 255) / 256;

    // one-time splits of inputs
    split_hl<<<(BATCH * INDIM / 4 + 255) / 256, 256>>>(x, xh, xl, BATCH * INDIM);
    split_hl<<<(UNITS * INDIM / 4 + 255) / 256, 256>>>(W_in, winh, winl, UNITS * INDIM);
    split_hl<<<(OUTDIM * UNITS / 4 + 255) / 256, 256>>>(W_out, woh, wol, OUTDIM * UNITS);

    // Input GEMM, rhs mode: d = x@W_in^T + b_in
    //   Ru0 = d + 0.1*b1 -> b2 (+splits -> P0), Rv0 = 11*relu(d) -> b3
    gemm_tc<<<gBig, 256, SMEM_GEMM>>>(xh, xl, winh, winl,
                                      b2, b3, P0h, P0l,
                                      BATCH, UNITS, INDIM, 1.0f, b_in, 0.0f,
                                      nullptr, 0.0f,
                                      bs[0], nullptr, 0.0f);

    // fp32 buffer roles per layer (see round-7 analysis):
    float* RU[4] = {b2, b0, b2, nullptr};  // Ru_l fp32 (input to u-GEMM of layer l)
    // Rv always lives in b3; V fp32 in b1.
    unsigned short* SP[2][2] = {{P0h, P0l}, {P1h, P1l}};
    int sp = 0;  // current split pair holding Ru_l splits

    for (int l = 0; l < 3; ++l) {
        const float* W = Ws[l];
        unsigned short* ah_ = SP[sp][0];     unsigned short* al_ = SP[sp][1];
        unsigned short* bh_ = SP[sp ^ 1][0]; unsigned short* bl_ = SP[sp ^ 1][1];

        // W -> (wh, wl) and W^T -> (s0h, s0l)
        weight_split_both<<<tgrid, tblk>>>(wh, wl, s0h, s0l, W, UNITS);
        // K = W^T W  (fp32)
        gemm_tc<<<gSmall, 256, SMEM_GEMM>>>(s0h, s0l, s0h, s0l, s1, nullptr,
                                            nullptr, nullptr,
                                            UNITS, UNITS, UNITS, 1.0f, nullptr, 0.0f,
                                            nullptr, 0.0f,
                                            nullptr, nullptr, 0.0f);
        // Minv = (1/c)(I - aK)
        scale_diag_split<<<sdBlocks, 256>>>(mih, mil, s1, -ACONST / CCONST,
                                            1.0f / CCONST, UNITS);

        // r = dt*Ru@W + Rv ; splits -> other pair
        gemm_tc<<<gBig, 256, SMEM_GEMM>>>(ah_, al_, s0h, s0l,
                                          nullptr, nullptr, bh_, bl_,
                                          BATCH, UNITS, UNITS, DT, nullptr, 0.0f,
                                          b3, 1.0f,
                                          nullptr, nullptr, 0.0f);
        // V = r @ Minv ; fp32 -> b1 (layers 0,1 only), splits -> first pair
        gemm_tc<<<gBig, 256, SMEM_GEMM>>>(bh_, bl_, mih, mil,
                                          (l < 2) ? b1 : nullptr, nullptr, ah_, al_,
                                          BATCH, UNITS, UNITS, 1.0f, nullptr, 0.0f,
                                          nullptr, 0.0f,
                                          nullptr, nullptr, 0.0f);
        // u_out = dt*V@W^T - Ru
        if (l < 2) {
            // rhs mode: Ru_{l+1} -> RU[l+1] (+splits -> other pair), Rv_{l+1} -> b3
            gemm_tc<<<gBig, 256, SMEM_GEMM>>>(ah_, al_, wh, wl,
                                              RU[l + 1], b3, bh_, bl_,
                                              BATCH, UNITS, UNITS, DT, nullptr, 0.0f,
                                              RU[l], -1.0f,
                                              bs[l + 1], b1, -1.0f);
        } else {
            // plain: splits of u_final -> other pair
            gemm_tc<<<gBig, 256, SMEM_GEMM>>>(ah_, al_, wh, wl,
                                              nullptr, nullptr, bh_, bl_,
                                              BATCH, UNITS, UNITS, DT, nullptr, 0.0f,
                                              RU[l], -1.0f,
                                              nullptr, nullptr, 0.0f);
        }
        sp ^= 1;  // Ru_{l+1} / u_final splits now live in the other pair
    }

    // logits = u @ W_out^T + b_out -> out ; softmax
    gemm_tc<<<gOut, 256, SMEM_GEMM>>>(SP[sp][0], SP[sp][1], woh, wol,
                                      out, nullptr, nullptr, nullptr,
                                      BATCH, OUTDIM, UNITS, 1.0f, b_out, 0.0f,
                                      nullptr, 0.0f,
                                      nullptr, nullptr, 0.0f);
    softmax_rows<<<BATCH, 256>>>(out, OUTDIM);
}

// round 9
// speedup vs baseline: 2.0993x; 2.0993x over previous
#include <cuda_runtime.h>
#include <cuda_bf16.h>
#include <cuda_fp16.h>
#include <cstddef>
#include <cstdint>

// ---------------------------------------------------------------------------
// TransNet, mma.sync fp16 single-pass GEMM (3x fewer MMAs than bf16 split).
//   Layer solve:  v·(cI + dt^2 W^T W) = rhs_v + dt·rhs_u@W
//   u_out = -u = dt·v@W^T - rhs_u,  v_out = -v
//   (cI + dt^2 K)^{-1} ≈ (1/c)(I - aK)   [first-order Neumann]
// Big GEMMs: fp16 operands, fp32 accumulate (rel err ~2^-12/GEMM, attenuated
// by the dt-scaled dataflow). K = W^T W stays bf16 3-term split (cheap).
// Minv stored as 1024*Minv in fp16 (off-diag would be subnormal), alpha/1024.
// ---------------------------------------------------------------------------

#define BATCH   8192
#define UNITS   1024
#define INDIM   2048
#define OUTDIM  1000

static const float DT     = 0.1f;
static const float CCONST = 11.0f;           // 1 + dt/eps
static const float ACONST = 0.01f / 11.0f;   // dt^2 / c

// ------------------------------- scratch (16B+ aligned) --------------------
__device__ __align__(256) float g_b0[BATCH * UNITS];
__device__ __align__(256) float g_b1[BATCH * UNITS];
__device__ __align__(256) float g_b2[BATCH * UNITS];
__device__ __align__(256) float g_b3[BATCH * UNITS];
__device__ __align__(256) float g_s1[UNITS * UNITS];    // K fp32

__device__ __align__(256) unsigned short g_x16[BATCH * INDIM];    // fp16 x
__device__ __align__(256) unsigned short g_win16[UNITS * INDIM];  // fp16 W_in
__device__ __align__(256) unsigned short g_wo16[OUTDIM * UNITS];  // fp16 W_out
__device__ __align__(256) unsigned short g_P0[BATCH * UNITS];     // fp16 act
__device__ __align__(256) unsigned short g_P1[BATCH * UNITS];     // fp16 act
__device__ __align__(256) unsigned short g_w16[UNITS * UNITS];    // fp16 W
__device__ __align__(256) unsigned short g_t16[UNITS * UNITS];    // fp16 W^T
__device__ __align__(256) unsigned short g_s0h[UNITS * UNITS];    // bf16 W^T hi
__device__ __align__(256) unsigned short g_s0l[UNITS * UNITS];    // bf16 W^T lo
__device__ __align__(256) unsigned short g_mi16[UNITS * UNITS];   // fp16 1024*Minv

// ------------------------------ helpers ------------------------------------
__device__ __forceinline__ uint32_t smem_u32(const void* p) {
    uint32_t a;
    asm("{ .reg .u64 t; cvta.to.shared.u64 t, %1; cvt.u32.u64 %0, t; }"
        : "=r"(a) : "l"(p));
    return a;
}

__device__ __forceinline__ void cp16(uint32_t dst, const void* src, bool inb) {
    int sz = inb ? 16 : 0;
    asm volatile(
        "{\n\t.reg .u64 g;\n\tcvta.to.global.u64 g, %1;\n\t"
        "cp.async.cg.shared.global [%0], [g], 16, %2;\n\t}"
        :: "r"(dst), "l"(src), "r"(sz) : "memory");
}
__device__ __forceinline__ void cp_commit() {
    asm volatile("cp.async.commit_group;" ::: "memory");
}
__device__ __forceinline__ void cp_wait1() {
    asm volatile("cp.async.wait_group 1;" ::: "memory");
}

__device__ __forceinline__ void mma_bf(float* d, const uint32_t* a, const uint32_t* b) {
    asm volatile(
        "mma.sync.aligned.m16n8k16.row.col.f32.bf16.bf16.f32 "
        "{%0,%1,%2,%3}, {%4,%5,%6,%7}, {%8,%9}, {%0,%1,%2,%3};"
        : "+f"(d[0]), "+f"(d[1]), "+f"(d[2]), "+f"(d[3])
        : "r"(a[0]), "r"(a[1]), "r"(a[2]), "r"(a[3]), "r"(b[0]), "r"(b[1]));
}
__device__ __forceinline__ void mma_h(float* d, const uint32_t* a, const uint32_t* b) {
    asm volatile(
        "mma.sync.aligned.m16n8k16.row.col.f32.f16.f16.f32 "
        "{%0,%1,%2,%3}, {%4,%5,%6,%7}, {%8,%9}, {%0,%1,%2,%3};"
        : "+f"(d[0]), "+f"(d[1]), "+f"(d[2]), "+f"(d[3])
        : "r"(a[0]), "r"(a[1]), "r"(a[2]), "r"(a[3]), "r"(b[0]), "r"(b[1]));
}

__device__ __forceinline__ void ldsm4(uint32_t* r, uint32_t addr) {
    asm volatile("ldmatrix.sync.aligned.m8n8.x4.shared.b16 {%0,%1,%2,%3}, [%4];"
        : "=r"(r[0]), "=r"(r[1]), "=r"(r[2]), "=r"(r[3]) : "r"(addr));
}

__device__ __forceinline__ void split1(float x, unsigned short& h, unsigned short& l) {
    __nv_bfloat16 hb = __float2bfloat16(x);
    h = __bfloat16_as_ushort(hb);
    l = __bfloat16_as_ushort(__float2bfloat16(x - __bfloat162float(hb)));
}
__device__ __forceinline__ unsigned short f2h(float x) {
    return __half_as_ushort(__float2half_rn(x));
}

// --------------------------- GEMM core --------------------------------------
// d[m,n] = alpha*sum_k A[m,k]B[n,k] (+bias[n]) (+add_scale*addp[m,n])
// SPLIT=true : bf16 3-term (Ah,Al,Bh,Bl).  SPLIT=false: fp16 single (Ah,Bh).
// Plain mode (bias2==null): C=d fp32, Crelu=relu(d), Ch=fp16(d).
// rhs mode (bias2!=null):   Ru = d + 0.1*bias2[n]; C=Ru, Ch=fp16(Ru);
//                           Crelu = 10*relu(d) + (vprev? svv*vprev : relu(d)).
// Tiles: BM=128, BN=64, BK=32. Rows 64B; swizzle chunk ^= (row>>1)&3.
#define BM 128
#define BN 64
#define BK 32
#define A_T 8192u
#define B_T 4096u
#define NSTAGE 3
#define SM_H (1024 + NSTAGE * (A_T + B_T))          // 37888
#define SM_S (1024 + NSTAGE * (2 * A_T + 2 * B_T))  // 74752

template <bool SPLIT>
__device__ __forceinline__ void gemm_core(
    const unsigned short* __restrict__ Ah, const unsigned short* __restrict__ Al,
    const unsigned short* __restrict__ Bh, const unsigned short* __restrict__ Bl,
    float* __restrict__ C, float* __restrict__ Crelu,
    unsigned short* __restrict__ Ch,
    int M, int N, int K, float alpha,
    const float* __restrict__ bias,
    const float* __restrict__ addp, float add_scale,
    const float* __restrict__ bias2, const float* __restrict__ vprev, float svv,
    char* smem)
{
    constexpr uint32_t STAGE = SPLIT ? (2 * A_T + 2 * B_T) : (A_T + B_T);
    constexpr uint32_t BOFF  = SPLIT ? 2 * A_T : A_T;    // B tile offset in stage
    const uint32_t sbase = smem_u32(smem) + 1024;
    const int tid  = threadIdx.x;
    const int wid  = tid >> 5;
    const int lane = tid & 31;
    const int bm = blockIdx.y * BM;
    const int bn = blockIdx.x * BN;
    const int nc = K / BK;

    auto issue_stage = [&](int c) {
        const int k0 = c * BK;
        const uint32_t sd = sbase + (c % NSTAGE) * STAGE;
        // A: 128 rows x 4 chunks = 512 slots -> 2 passes
#pragma unroll
        for (int p = 0; p < 2; ++p) {
            int s = tid + p * 256;
            int row = s >> 2, ch = s & 3;
            uint32_t off = (uint32_t)row * 64u + (uint32_t)((ch ^ ((row >> 1) & 3)) << 4);
            cp16(sd + off, Ah + (size_t)(bm + row) * K + k0 + ch * 8, bm + row < M);
            if (SPLIT)
                cp16(sd + A_T + off, Al + (size_t)(bm + row) * K + k0 + ch * 8,
                     bm + row < M);
        }
        // B: 64 rows x 4 chunks = 256 slots -> 1 pass
        {
            int row = tid >> 2, ch = tid & 3;
            uint32_t off = (uint32_t)row * 64u + (uint32_t)((ch ^ ((row >> 1) & 3)) << 4);
            cp16(sd + BOFF + off, Bh + (size_t)(bn + row) * K + k0 + ch * 8,
                 bn + row < N);
            if (SPLIT)
                cp16(sd + BOFF + B_T + off, Bl + (size_t)(bn + row) * K + k0 + ch * 8,
                     bn + row < N);
        }
        cp_commit();
    };

    // warp tiling: warp (wm, wn) owns rows [wm*32,+32) x cols [wn*32,+32)
    const int wm = wid & 3;
    const int wn = wid >> 2;
    const int r  = lane >> 2;
    const int c2 = (lane & 3) * 2;

    const int q    = lane >> 3;
    const int rin  = lane & 7;
    const int rsw  = rin >> 1;
    const uint32_t a_row = (uint32_t)(wm * 32 + (q & 1) * 8 + rin) * 64u;
    const int a_sel = q >> 1;
    const uint32_t b_row = (uint32_t)(wn * 32 + (q >> 1) * 8 + rin) * 64u;
    const int b_sel = q & 1;

    float acc[2][4][4];
#pragma unroll
    for (int a = 0; a < 2; ++a)
#pragma unroll
        for (int b = 0; b < 4; ++b)
#pragma unroll
            for (int k = 0; k < 4; ++k) acc[a][b][k] = 0.0f;

    issue_stage(0);
    if (nc > 1) issue_stage(1);

    for (int c = 0; c < nc; ++c) {
        cp_wait1();
        __syncthreads();
        if (c + 2 < nc) issue_stage(c + 2);

        const uint32_t st  = sbase + (c % NSTAGE) * STAGE;
        const uint32_t tAh = st;
        const uint32_t tBh = st + BOFF;

#pragma unroll
        for (int ks = 0; ks < 2; ++ks) {
            const uint32_t aoff = (uint32_t)(((ks * 2 + a_sel) ^ rsw)) << 4;
            const uint32_t boff = (uint32_t)(((ks * 2 + b_sel) ^ rsw)) << 4;

            uint32_t ah[2][4];
            ldsm4(ah[0], tAh + a_row + aoff);
            ldsm4(ah[1], tAh + a_row + 1024u + aoff);
            uint32_t bh[4][2];
#pragma unroll
            for (int p = 0; p < 2; ++p) {
                uint32_t r4[4];
                ldsm4(r4, tBh + b_row + (uint32_t)p * 1024u + boff);
                bh[2 * p][0] = r4[0]; bh[2 * p][1] = r4[1];
                bh[2 * p + 1][0] = r4[2]; bh[2 * p + 1][1] = r4[3];
            }

            if (SPLIT) {
                uint32_t al[2][4], bl[4][2];
                ldsm4(al[0], tAh + A_T + a_row + aoff);
                ldsm4(al[1], tAh + A_T + a_row + 1024u + aoff);
#pragma unroll
                for (int p = 0; p < 2; ++p) {
                    uint32_t r4[4];
                    ldsm4(r4, tBh + B_T + b_row + (uint32_t)p * 1024u + boff);
                    bl[2 * p][0] = r4[0]; bl[2 * p][1] = r4[1];
                    bl[2 * p + 1][0] = r4[2]; bl[2 * p + 1][1] = r4[3];
                }
#pragma unroll
                for (int nt = 0; nt < 4; ++nt) {
                    mma_bf(acc[0][nt], ah[0], bh[nt]);
                    mma_bf(acc[1][nt], ah[1], bh[nt]);
                }
#pragma unroll
                for (int nt = 0; nt < 4; ++nt) {
                    mma_bf(acc[0][nt], al[0], bh[nt]);
                    mma_bf(acc[1][nt], al[1], bh[nt]);
                }
#pragma unroll
                for (int nt = 0; nt < 4; ++nt) {
                    mma_bf(acc[0][nt], ah[0], bl[nt]);
                    mma_bf(acc[1][nt], ah[1], bl[nt]);
                }
            } else {
#pragma unroll
                for (int nt = 0; nt < 4; ++nt) {
                    mma_h(acc[0][nt], ah[0], bh[nt]);
                    mma_h(acc[1][nt], ah[1], bh[nt]);
                }
            }
        }
    }
    __syncthreads();

    // epilogue
#pragma unroll
    for (int mt = 0; mt < 2; ++mt) {
#pragma unroll
        for (int nt = 0; nt < 4; ++nt) {
            const int col = bn + wn * 32 + nt * 8 + c2;
            if (col >= N) continue;
            float bx = 0.f, by = 0.f;
            if (bias) { bx = bias[col]; by = bias[col + 1]; }
#pragma unroll
            for (int h = 0; h < 2; ++h) {
                const int m = bm + wm * 32 + mt * 16 + r + h * 8;
                float d0 = alpha * acc[mt][nt][2 * h + 0] + bx;
                float d1 = alpha * acc[mt][nt][2 * h + 1] + by;
                size_t idx = (size_t)m * N + col;
                if (addp) {
                    d0 += add_scale * addp[idx];
                    d1 += add_scale * addp[idx + 1];
                }
                if (bias2) {
                    float r0 = fmaxf(d0, 0.f), r1 = fmaxf(d1, 0.f);
                    float rv0 = 10.f * r0, rv1 = 10.f * r1;
                    if (vprev) {
                        float2 vp = *(const float2*)(vprev + idx);
                        rv0 += svv * vp.x; rv1 += svv * vp.y;
                    } else {
                        rv0 += r0; rv1 += r1;
                    }
                    *(float2*)(Crelu + idx) = make_float2(rv0, rv1);
                    d0 += 0.1f * bias2[col];
                    d1 += 0.1f * bias2[col + 1];
                } else if (Crelu) {
                    *(float2*)(Crelu + idx) =
                        make_float2(fmaxf(d0, 0.f), fmaxf(d1, 0.f));
                }
                if (C) *(float2*)(C + idx) = make_float2(d0, d1);
                if (Ch) *(ushort2*)(Ch + idx) = make_ushort2(f2h(d0), f2h(d1));
            }
        }
    }
}

// fp16 single-pass GEMM, 3 CTAs/SM
__global__ __launch_bounds__(256, 3) void gemm_h16(
    const unsigned short* __restrict__ A, const unsigned short* __restrict__ B,
    float* C, float* Crelu, unsigned short* Ch,
    int M, int N, int K, float alpha,
    const float* bias, const float* addp, float add_scale,
    const float* bias2, const float* vprev, float svv)
{
    extern __shared__ char smem[];
    gemm_core<false>(A, nullptr, B, nullptr, C, Crelu, Ch, M, N, K, alpha,
                     bias, addp, add_scale, bias2, vprev, svv, smem);
}

// bf16 3-term split GEMM (small K = W^T W only), 2 CTAs/SM
__global__ __launch_bounds__(256, 2) void gemm_s16(
    const unsigned short* __restrict__ Ah, const unsigned short* __restrict__ Al,
    const unsigned short* __restrict__ Bh, const unsigned short* __restrict__ Bl,
    float* C, int M, int N, int K, float alpha)
{
    extern __shared__ char smem[];
    gemm_core<true>(Ah, Al, Bh, Bl, C, nullptr, nullptr, M, N, K, alpha,
                    nullptr, nullptr, 0.f, nullptr, nullptr, 0.f, smem);
}

// ----------------------------- elementwise ---------------------------------
__global__ void tofp16(const float* __restrict__ src,
                       unsigned short* __restrict__ dst, int n)
{
    int i = blockIdx.x * blockDim.x + threadIdx.x;
    if (i * 4 < n) {
        float4 v = *(const float4*)(src + i * 4);
        *(ushort4*)(dst + i * 4) =
            make_ushort4(f2h(v.x), f2h(v.y), f2h(v.z), f2h(v.w));
    }
}

// one pass over W: fp16 W -> w16; fp16 W^T -> t16; bf16 splits of W^T -> s0h/s0l
__global__ void weight_prep(unsigned short* __restrict__ w16,
                            unsigned short* __restrict__ t16,
                            unsigned short* __restrict__ s0h,
                            unsigned short* __restrict__ s0l,
                            const float* __restrict__ W, int n)
{
    __shared__ float t[32][33];
    int x = blockIdx.x * 32 + threadIdx.x;
    int y = blockIdx.y * 32 + threadIdx.y;
    float v = W[(size_t)y * n + x];
    t[threadIdx.y][threadIdx.x] = v;
    w16[(size_t)y * n + x] = f2h(v);
    __syncthreads();
    int ox = blockIdx.y * 32 + threadIdx.x;
    int oy = blockIdx.x * 32 + threadIdx.y;
    float tv = t[threadIdx.x][threadIdx.y];
    t16[(size_t)oy * n + ox] = f2h(tv);
    unsigned short h, l;
    split1(tv, h, l);
    s0h[(size_t)oy * n + ox] = h;
    s0l[(size_t)oy * n + ox] = l;
}

// mi16 = fp16( scale*K + diag*I )   [stores 1024*Minv]
__global__ void scale_diag16(unsigned short* __restrict__ d16,
                             const float* __restrict__ src,
                             float scale, float diag, int dim)
{
    int i = blockIdx.x * blockDim.x + threadIdx.x;
    if (i < dim * dim) {
        float v = scale * src[i];
        if ((i / dim) == (i % dim)) v += diag;
        d16[i] = f2h(v);
    }
}

__global__ void softmax_rows(float* __restrict__ data, int cols)
{
    int row = blockIdx.x;
    float* d = data + (size_t)row * cols;
    __shared__ float sm[32];
    int tid = threadIdx.x, lane = tid & 31, warp = tid >> 5;
    int nwarp = blockDim.x >> 5;

    float m = -3.4e38f;
    for (int i = tid; i < cols; i += blockDim.x) m = fmaxf(m, d[i]);
#pragma unroll
    for (int o = 16; o; o >>= 1) m = fmaxf(m, __shfl_xor_sync(0xffffffffu, m, o));
    if (lane == 0) sm[warp] = m;
    __syncthreads();
    if (warp == 0) {
        float t = (lane < nwarp) ? sm[lane] : -3.4e38f;
#pragma unroll
        for (int o = 16; o; o >>= 1) t = fmaxf(t, __shfl_xor_sync(0xffffffffu, t, o));
        if (lane == 0) sm[0] = t;
    }
    __syncthreads();
    float mx = sm[0];
    __syncthreads();

    float s = 0.0f;
    for (int i = tid; i < cols; i += blockDim.x) {
        float e = expf(d[i] - mx);
        d[i] = e;
        s += e;
    }
#pragma unroll
    for (int o = 16; o; o >>= 1) s += __shfl_xor_sync(0xffffffffu, s, o);
    if (lane == 0) sm[warp] = s;
    __syncthreads();
    if (warp == 0) {
        float t = (lane < nwarp) ? sm[lane] : 0.0f;
#pragma unroll
        for (int o = 16; o; o >>= 1) t += __shfl_xor_sync(0xffffffffu, t, o);
        if (lane == 0) sm[0] = t;
    }
    __syncthreads();
    float inv = 1.0f / sm[0];
    for (int i = tid; i < cols; i += blockDim.x) d[i] *= inv;
}

// ---------------------------------------------------------------------------
extern "C" void kernel_launch(void* const* d_in, const int* in_sizes, int n_in,
                              void* d_out, int out_size)
{
    const float* x     = (const float*)d_in[0];
    const float* W_in  = (const float*)d_in[1];
    const float* b_in  = (const float*)d_in[2];
    const float* Ws[3] = {(const float*)d_in[3], (const float*)d_in[5], (const float*)d_in[7]};
    const float* bs[3] = {(const float*)d_in[4], (const float*)d_in[6], (const float*)d_in[8]};
    const float* W_out = (const float*)d_in[9];
    const float* b_out = (const float*)d_in[10];
    float* out = (float*)d_out;

    cudaFuncSetAttribute(gemm_h16, cudaFuncAttributeMaxDynamicSharedMemorySize, SM_H);
    cudaFuncSetAttribute(gemm_s16, cudaFuncAttributeMaxDynamicSharedMemorySize, SM_S);

    float *b0, *b1, *b2, *b3, *s1;
    cudaGetSymbolAddress((void**)&b0, g_b0);
    cudaGetSymbolAddress((void**)&b1, g_b1);
    cudaGetSymbolAddress((void**)&b2, g_b2);
    cudaGetSymbolAddress((void**)&b3, g_b3);
    cudaGetSymbolAddress((void**)&s1, g_s1);
    unsigned short *x16, *win16, *wo16, *P0, *P1, *w16, *t16, *s0h, *s0l, *mi16;
    cudaGetSymbolAddress((void**)&x16, g_x16);
    cudaGetSymbolAddress((void**)&win16, g_win16);
    cudaGetSymbolAddress((void**)&wo16, g_wo16);
    cudaGetSymbolAddress((void**)&P0, g_P0);
    cudaGetSymbolAddress((void**)&P1, g_P1);
    cudaGetSymbolAddress((void**)&w16, g_w16);
    cudaGetSymbolAddress((void**)&t16, g_t16);
    cudaGetSymbolAddress((void**)&s0h, g_s0h);
    cudaGetSymbolAddress((void**)&s0l, g_s0l);
    cudaGetSymbolAddress((void**)&mi16, g_mi16);

    dim3 gBig(UNITS / BN, BATCH / BM);                 // (16, 64)
    dim3 gSmall(UNITS / BN, UNITS / BM);               // (16, 8)
    dim3 gOut((OUTDIM + BN - 1) / BN, BATCH / BM);     // (16, 64)
    dim3 tblk(32, 32), tgrid(UNITS / 32, UNITS / 32);
    int sdBlocks = (UNITS * UNITS + 255) / 256;

    // one-time fp16 conversions
    tofp16<<<(BATCH * INDIM / 4 + 255) / 256, 256>>>(x, x16, BATCH * INDIM);
    tofp16<<<(UNITS * INDIM / 4 + 255) / 256, 256>>>(W_in, win16, UNITS * INDIM);
    tofp16<<<(OUTDIM * UNITS / 4 + 255) / 256, 256>>>(W_out, wo16, OUTDIM * UNITS);

    // Input GEMM, rhs mode: d = x@W_in^T + b_in
    //   Ru0 = d + 0.1*bs0 -> b2 (+fp16 -> P0), Rv0 = 11*relu(d) -> b3
    gemm_h16<<<gBig, 256, SM_H>>>(x16, win16, b2, b3, P0,
                                  BATCH, UNITS, INDIM, 1.0f, b_in,
                                  nullptr, 0.0f, bs[0], nullptr, 0.0f);

    float* RU[4] = {b2, b0, b2, nullptr};   // Ru_l fp32
    unsigned short* P[2] = {P0, P1};
    int sp = 0;   // P[sp] holds current layer's Ru fp16

    for (int l = 0; l < 3; ++l) {
        const float* W = Ws[l];
        unsigned short* Pc = P[sp];
        unsigned short* Po = P[sp ^ 1];

        weight_prep<<<tgrid, tblk>>>(w16, t16, s0h, s0l, W, UNITS);
        // K = W^T W (bf16 3-term, fp32 out)
        gemm_s16<<<gSmall, 256, SM_S>>>(s0h, s0l, s0h, s0l, s1,
                                        UNITS, UNITS, UNITS, 1.0f);
        // mi16 = fp16(1024 * Minv) = (1024/c)I - (1024 a/c)K
        scale_diag16<<<sdBlocks, 256>>>(mi16, s1, -1024.0f * ACONST / CCONST,
                                        1024.0f / CCONST, UNITS);

        // r = dt*Ru@W + Rv  (B = W^T) -> fp16 Po
        gemm_h16<<<gBig, 256, SM_H>>>(Pc, t16, nullptr, nullptr, Po,
                                      BATCH, UNITS, UNITS, DT, nullptr,
                                      b3, 1.0f, nullptr, nullptr, 0.0f);
        // V = r @ (1024*Minv) / 1024 -> fp32 b1 (l<2) + fp16 Pc
        gemm_h16<<<gBig, 256, SM_H>>>(Po, mi16, (l < 2) ? b1 : nullptr, nullptr, Pc,
                                      BATCH, UNITS, UNITS, 1.0f / 1024.0f, nullptr,
                                      nullptr, 0.0f, nullptr, nullptr, 0.0f);
        // u_out = dt*V@W^T - Ru
        if (l < 2) {
            gemm_h16<<<gBig, 256, SM_H>>>(Pc, w16, RU[l + 1], b3, Po,
                                          BATCH, UNITS, UNITS, DT, nullptr,
                                          RU[l], -1.0f, bs[l + 1], b1, -1.0f);
        } else {
            gemm_h16<<<gBig, 256, SM_H>>>(Pc, w16, nullptr, nullptr, Po,
                                          BATCH, UNITS, UNITS, DT, nullptr,
                                          RU[l], -1.0f, nullptr, nullptr, 0.0f);
        }
        sp ^= 1;
    }

    // logits = u @ W_out^T + b_out -> out ; softmax
    gemm_h16<<<gOut, 256, SM_H>>>(P[sp], wo16, out, nullptr, nullptr,
                                  BATCH, OUTDIM, UNITS, 1.0f, b_out,
                                  nullptr, 0.0f, nullptr, nullptr, 0.0f);
    softmax_rows<<<BATCH, 256>>>(out, OUTDIM);
}

// round 10
// speedup vs baseline: 2.1545x; 1.0263x over previous
#include <cuda_runtime.h>
#include <cuda_bf16.h>
#include <cuda_fp16.h>
#include <cstddef>
#include <cstdint>

// ---------------------------------------------------------------------------
// TransNet, mma.sync fp16 GEMM, warp tile 32x64, strength-reduced addressing.
//   Layer solve:  v·(cI + dt^2 W^T W) = rhs_v + dt·rhs_u@W
//   u_out = -u = dt·v@W^T - rhs_u,  v_out = -v
//   (cI + dt^2 K)^{-1} ≈ (1/c)(I - aK)   [first-order Neumann]
// All GEMMs fp16 operands, fp32 accumulate. Minv stored as 1024*Minv in fp16
// (off-diag would be subnormal), 1/1024 folded into alpha.
// Tiles: BM=128, BN=128, BK=32 (64B rows, chunk-XOR swizzle), 3-stage cp.async.
// ---------------------------------------------------------------------------

#define BATCH   8192
#define UNITS   1024
#define INDIM   2048
#define OUTDIM  1000

static const float DT     = 0.1f;
static const float CCONST = 11.0f;           // 1 + dt/eps
static const float ACONST = 0.01f / 11.0f;   // dt^2 / c

// ------------------------------- scratch (16B+ aligned) --------------------
__device__ __align__(256) float g_b0[BATCH * UNITS];
__device__ __align__(256) float g_b1[BATCH * UNITS];
__device__ __align__(256) float g_b2[BATCH * UNITS];
__device__ __align__(256) float g_b3[BATCH * UNITS];
__device__ __align__(256) float g_s1[UNITS * UNITS];    // K fp32

__device__ __align__(256) unsigned short g_x16[BATCH * INDIM];    // fp16 x
__device__ __align__(256) unsigned short g_win16[UNITS * INDIM];  // fp16 W_in
__device__ __align__(256) unsigned short g_wo16[OUTDIM * UNITS];  // fp16 W_out
__device__ __align__(256) unsigned short g_P0[BATCH * UNITS];     // fp16 act
__device__ __align__(256) unsigned short g_P1[BATCH * UNITS];     // fp16 act
__device__ __align__(256) unsigned short g_w16[UNITS * UNITS];    // fp16 W
__device__ __align__(256) unsigned short g_t16[UNITS * UNITS];    // fp16 W^T
__device__ __align__(256) unsigned short g_mi16[UNITS * UNITS];   // fp16 1024*Minv

// ------------------------------ helpers ------------------------------------
__device__ __forceinline__ uint32_t smem_u32(const void* p) {
    uint32_t a;
    asm("{ .reg .u64 t; cvta.to.shared.u64 t, %1; cvt.u32.u64 %0, t; }"
        : "=r"(a) : "l"(p));
    return a;
}

__device__ __forceinline__ void cp16(uint32_t dst, const void* src, bool inb) {
    int sz = inb ? 16 : 0;
    asm volatile(
        "{\n\t.reg .u64 g;\n\tcvta.to.global.u64 g, %1;\n\t"
        "cp.async.cg.shared.global [%0], [g], 16, %2;\n\t}"
        :: "r"(dst), "l"(src), "r"(sz) : "memory");
}
__device__ __forceinline__ void cp_commit() {
    asm volatile("cp.async.commit_group;" ::: "memory");
}
__device__ __forceinline__ void cp_wait1() {
    asm volatile("cp.async.wait_group 1;" ::: "memory");
}

__device__ __forceinline__ void mma_h(float* d, const uint32_t* a, const uint32_t* b) {
    asm volatile(
        "mma.sync.aligned.m16n8k16.row.col.f32.f16.f16.f32 "
        "{%0,%1,%2,%3}, {%4,%5,%6,%7}, {%8,%9}, {%0,%1,%2,%3};"
        : "+f"(d[0]), "+f"(d[1]), "+f"(d[2]), "+f"(d[3])
        : "r"(a[0]), "r"(a[1]), "r"(a[2]), "r"(a[3]), "r"(b[0]), "r"(b[1]));
}

__device__ __forceinline__ void ldsm4(uint32_t* r, uint32_t addr) {
    asm volatile("ldmatrix.sync.aligned.m8n8.x4.shared.b16 {%0,%1,%2,%3}, [%4];"
        : "=r"(r[0]), "=r"(r[1]), "=r"(r[2]), "=r"(r[3]) : "r"(addr));
}

__device__ __forceinline__ unsigned short f2h(float x) {
    return __half_as_ushort(__float2half_rn(x));
}

// --------------------------- GEMM kernel -------------------------------------
// d[m,n] = alpha*sum_k A[m,k]B[n,k] (+bias[n]) (+add_scale*addp[m,n])
// Plain mode (bias2==null): C=d fp32, Crelu=relu(d), Ch=fp16(d).
// rhs mode (bias2!=null):   Ru = d + 0.1*bias2[n]; C=Ru, Ch=fp16(Ru);
//                           Crelu = 10*relu(d) + (vprev? svv*vprev : relu(d)).
// Tiles: BM=128, BN=128, BK=32; warp tile 32x64 (4m x 2n warps).
#define BM 128
#define BN 128
#define BK 32
#define A_T 8192u
#define STAGE 16384u
#define NSTAGE 3
#define SM_H (1024 + NSTAGE * STAGE)    // 50176

__global__ __launch_bounds__(256, 2) void gemm_h16(
    const unsigned short* __restrict__ A, const unsigned short* __restrict__ B,
    float* __restrict__ C, float* __restrict__ Crelu,
    unsigned short* __restrict__ Ch,
    int M, int N, int K, float alpha,
    const float* __restrict__ bias,
    const float* __restrict__ addp, float add_scale,
    const float* __restrict__ bias2, const float* __restrict__ vprev, float svv)
{
    extern __shared__ char smem[];
    const uint32_t sbase = smem_u32(smem) + 1024;
    const int tid  = threadIdx.x;
    const int wid  = tid >> 5;
    const int lane = tid & 31;
    const int bm = blockIdx.y * BM;
    const int bn = blockIdx.x * BN;
    const int nc = K / BK;

    // ---- cp.async: precomputed per-thread slots -----------------------------
    const int arow = tid >> 2;          // 0..63
    const int ach  = tid & 3;           // 16B chunk in 64B row
    const unsigned short* gA0 = A + (size_t)(bm + arow) * K + ach * 8;
    const unsigned short* gA1 = A + (size_t)(bm + arow + 64) * K + ach * 8;
    const unsigned short* gB0 = B + (size_t)(bn + arow) * K + ach * 8;
    const unsigned short* gB1 = B + (size_t)(bn + arow + 64) * K + ach * 8;
    const bool inA0 = (bm + arow) < M,      inA1 = (bm + arow + 64) < M;
    const bool inB0 = (bn + arow) < N,      inB1 = (bn + arow + 64) < N;
    const uint32_t swz  = (uint32_t)((ach ^ ((arow >> 1) & 3)) << 4);
    const uint32_t ofA0 = (uint32_t)arow * 64u + swz;        // rows share swizzle
    const uint32_t ofA1 = ofA0 + 64u * 64u;                  // (+64 rows: same swz)
    const uint32_t stb0 = sbase, stb1 = sbase + STAGE, stb2 = sbase + 2 * STAGE;

    auto issue_stage = [&](int c, uint32_t sd) {
        const int k0 = c * BK;
        cp16(sd + ofA0,        gA0 + k0, inA0);
        cp16(sd + ofA1,        gA1 + k0, inA1);
        cp16(sd + A_T + ofA0,  gB0 + k0, inB0);
        cp16(sd + A_T + ofA1,  gB1 + k0, inB1);
        cp_commit();
    };

    // ---- warp tiling: warp (wm, wn) = rows [wm*32,+32) x cols [wn*64,+64) ---
    const int wm = wid & 3;
    const int wn = wid >> 2;
    const int r  = lane >> 2;
    const int c2 = (lane & 3) * 2;

    const int q    = lane >> 3;
    const int rin  = lane & 7;
    const int rsw  = rin >> 1;
    const uint32_t a_row = (uint32_t)(wm * 32 + (q & 1) * 8 + rin) * 64u;
    const int a_sel = q >> 1;
    const uint32_t b_row = (uint32_t)(wn * 64 + (q >> 1) * 8 + rin) * 64u + A_T;
    const int b_sel = q & 1;
    // per-ks swizzled chunk offsets (ks = 0,1)
    const uint32_t aof0 = (uint32_t)((a_sel ^ rsw)) << 4;
    const uint32_t aof1 = (uint32_t)(((2 + a_sel) ^ rsw)) << 4;
    const uint32_t bof0 = (uint32_t)((b_sel ^ rsw)) << 4;
    const uint32_t bof1 = (uint32_t)(((2 + b_sel) ^ rsw)) << 4;

    float acc[2][8][4];
#pragma unroll
    for (int a = 0; a < 2; ++a)
#pragma unroll
        for (int b = 0; b < 8; ++b)
#pragma unroll
            for (int k = 0; k < 4; ++k) acc[a][b][k] = 0.0f;

    issue_stage(0, stb0);
    if (nc > 1) issue_stage(1, stb1);

    uint32_t cur = stb0, nxt1 = stb1, nxt2 = stb2;
    for (int c = 0; c < nc; ++c) {
        cp_wait1();
        __syncthreads();
        if (c + 2 < nc) issue_stage(c + 2, nxt2);

        const uint32_t tA = cur;
        const uint32_t tB = cur;   // b_row already includes A_T

#pragma unroll
        for (int ks = 0; ks < 2; ++ks) {
            const uint32_t aoff = ks ? aof1 : aof0;
            const uint32_t boff = ks ? bof1 : bof0;

            uint32_t a[2][4];
            ldsm4(a[0], tA + a_row + aoff);
            ldsm4(a[1], tA + a_row + 1024u + aoff);

            uint32_t b[8][2];
#pragma unroll
            for (int p = 0; p < 4; ++p) {
                uint32_t r4[4];
                ldsm4(r4, tB + b_row + (uint32_t)p * 1024u + boff);
                b[2 * p][0] = r4[0]; b[2 * p][1] = r4[1];
                b[2 * p + 1][0] = r4[2]; b[2 * p + 1][1] = r4[3];
            }

#pragma unroll
            for (int nt = 0; nt < 8; ++nt) {
                mma_h(acc[0][nt], a[0], b[nt]);
                mma_h(acc[1][nt], a[1], b[nt]);
            }
        }
        // rotate stage pointers
        uint32_t t = cur; cur = nxt1; nxt1 = nxt2; nxt2 = t;
    }
    __syncthreads();

    // ---- epilogue -----------------------------------------------------------
#pragma unroll
    for (int mt = 0; mt < 2; ++mt) {
#pragma unroll
        for (int nt = 0; nt < 8; ++nt) {
            const int col = bn + wn * 64 + nt * 8 + c2;
            if (col >= N) continue;
            float bx = 0.f, by = 0.f;
            if (bias) { bx = bias[col]; by = bias[col + 1]; }
#pragma unroll
            for (int h = 0; h < 2; ++h) {
                const int m = bm + wm * 32 + mt * 16 + r + h * 8;
                float d0 = alpha * acc[mt][nt][2 * h + 0] + bx;
                float d1 = alpha * acc[mt][nt][2 * h + 1] + by;
                size_t idx = (size_t)m * N + col;
                if (addp) {
                    d0 += add_scale * addp[idx];
                    d1 += add_scale * addp[idx + 1];
                }
                if (bias2) {
                    float r0 = fmaxf(d0, 0.f), r1 = fmaxf(d1, 0.f);
                    float rv0 = 10.f * r0, rv1 = 10.f * r1;
                    if (vprev) {
                        float2 vp = *(const float2*)(vprev + idx);
                        rv0 += svv * vp.x; rv1 += svv * vp.y;
                    } else {
                        rv0 += r0; rv1 += r1;
                    }
                    *(float2*)(Crelu + idx) = make_float2(rv0, rv1);
                    d0 += 0.1f * bias2[col];
                    d1 += 0.1f * bias2[col + 1];
                } else if (Crelu) {
                    *(float2*)(Crelu + idx) =
                        make_float2(fmaxf(d0, 0.f), fmaxf(d1, 0.f));
                }
                if (C) *(float2*)(C + idx) = make_float2(d0, d1);
                if (Ch) *(ushort2*)(Ch + idx) = make_ushort2(f2h(d0), f2h(d1));
            }
        }
    }
}

// ----------------------------- elementwise ---------------------------------
__global__ void tofp16(const float* __restrict__ src,
                       unsigned short* __restrict__ dst, int n)
{
    int i = blockIdx.x * blockDim.x + threadIdx.x;
    if (i * 4 < n) {
        float4 v = *(const float4*)(src + i * 4);
        *(ushort4*)(dst + i * 4) =
            make_ushort4(f2h(v.x), f2h(v.y), f2h(v.z), f2h(v.w));
    }
}

// one pass over W: fp16 W -> w16; fp16 W^T -> t16
__global__ void weight_prep(unsigned short* __restrict__ w16,
                            unsigned short* __restrict__ t16,
                            const float* __restrict__ W, int n)
{
    __shared__ float t[32][33];
    int x = blockIdx.x * 32 + threadIdx.x;
    int y = blockIdx.y * 32 + threadIdx.y;
    float v = W[(size_t)y * n + x];
    t[threadIdx.y][threadIdx.x] = v;
    w16[(size_t)y * n + x] = f2h(v);
    __syncthreads();
    int ox = blockIdx.y * 32 + threadIdx.x;
    int oy = blockIdx.x * 32 + threadIdx.y;
    t16[(size_t)oy * n + ox] = f2h(t[threadIdx.x][threadIdx.y]);
}

// mi16 = fp16( scale*K + diag*I )   [stores 1024*Minv]
__global__ void scale_diag16(unsigned short* __restrict__ d16,
                             const float* __restrict__ src,
                             float scale, float diag, int dim)
{
    int i = blockIdx.x * blockDim.x + threadIdx.x;
    if (i < dim * dim) {
        float v = scale * src[i];
        if ((i / dim) == (i % dim)) v += diag;
        d16[i] = f2h(v);
    }
}

__global__ void softmax_rows(float* __restrict__ data, int cols)
{
    int row = blockIdx.x;
    float* d = data + (size_t)row * cols;
    __shared__ float sm[32];
    int tid = threadIdx.x, lane = tid & 31, warp = tid >> 5;
    int nwarp = blockDim.x >> 5;

    float m = -3.4e38f;
    for (int i = tid; i < cols; i += blockDim.x) m = fmaxf(m, d[i]);
#pragma unroll
    for (int o = 16; o; o >>= 1) m = fmaxf(m, __shfl_xor_sync(0xffffffffu, m, o));
    if (lane == 0) sm[warp] = m;
    __syncthreads();
    if (warp == 0) {
        float t = (lane < nwarp) ? sm[lane] : -3.4e38f;
#pragma unroll
        for (int o = 16; o; o >>= 1) t = fmaxf(t, __shfl_xor_sync(0xffffffffu, t, o));
        if (lane == 0) sm[0] = t;
    }
    __syncthreads();
    float mx = sm[0];
    __syncthreads();

    float s = 0.0f;
    for (int i = tid; i < cols; i += blockDim.x) {
        float e = expf(d[i] - mx);
        d[i] = e;
        s += e;
    }
#pragma unroll
    for (int o = 16; o; o >>= 1) s += __shfl_xor_sync(0xffffffffu, s, o);
    if (lane == 0) sm[warp] = s;
    __syncthreads();
    if (warp == 0) {
        float t = (lane < nwarp) ? sm[lane] : 0.0f;
#pragma unroll
        for (int o = 16; o; o >>= 1) t += __shfl_xor_sync(0xffffffffu, t, o);
        if (lane == 0) sm[0] = t;
    }
    __syncthreads();
    float inv = 1.0f / sm[0];
    for (int i = tid; i < cols; i += blockDim.x) d[i] *= inv;
}

// ---------------------------------------------------------------------------
extern "C" void kernel_launch(void* const* d_in, const int* in_sizes, int n_in,
                              void* d_out, int out_size)
{
    const float* x     = (const float*)d_in[0];
    const float* W_in  = (const float*)d_in[1];
    const float* b_in  = (const float*)d_in[2];
    const float* Ws[3] = {(const float*)d_in[3], (const float*)d_in[5], (const float*)d_in[7]};
    const float* bs[3] = {(const float*)d_in[4], (const float*)d_in[6], (const float*)d_in[8]};
    const float* W_out = (const float*)d_in[9];
    const float* b_out = (const float*)d_in[10];
    float* out = (float*)d_out;

    cudaFuncSetAttribute(gemm_h16, cudaFuncAttributeMaxDynamicSharedMemorySize, SM_H);

    float *b0, *b1, *b2, *b3, *s1;
    cudaGetSymbolAddress((void**)&b0, g_b0);
    cudaGetSymbolAddress((void**)&b1, g_b1);
    cudaGetSymbolAddress((void**)&b2, g_b2);
    cudaGetSymbolAddress((void**)&b3, g_b3);
    cudaGetSymbolAddress((void**)&s1, g_s1);
    unsigned short *x16, *win16, *wo16, *P0, *P1, *w16, *t16, *mi16;
    cudaGetSymbolAddress((void**)&x16, g_x16);
    cudaGetSymbolAddress((void**)&win16, g_win16);
    cudaGetSymbolAddress((void**)&wo16, g_wo16);
    cudaGetSymbolAddress((void**)&P0, g_P0);
    cudaGetSymbolAddress((void**)&P1, g_P1);
    cudaGetSymbolAddress((void**)&w16, g_w16);
    cudaGetSymbolAddress((void**)&t16, g_t16);
    cudaGetSymbolAddress((void**)&mi16, g_mi16);

    dim3 gBig(UNITS / BN, BATCH / BM);                 // (8, 64)
    dim3 gSmall(UNITS / BN, UNITS / BM);               // (8, 8)
    dim3 gOut((OUTDIM + BN - 1) / BN, BATCH / BM);     // (8, 64)
    dim3 tblk(32, 32), tgrid(UNITS / 32, UNITS / 32);
    int sdBlocks = (UNITS * UNITS + 255) / 256;

    // one-time fp16 conversions
    tofp16<<<(BATCH * INDIM / 4 + 255) / 256, 256>>>(x, x16, BATCH * INDIM);
    tofp16<<<(UNITS * INDIM / 4 + 255) / 256, 256>>>(W_in, win16, UNITS * INDIM);
    tofp16<<<(OUTDIM * UNITS / 4 + 255) / 256, 256>>>(W_out, wo16, OUTDIM * UNITS);

    // Input GEMM, rhs mode: d = x@W_in^T + b_in
    //   Ru0 = d + 0.1*bs0 -> b2 (+fp16 -> P0), Rv0 = 11*relu(d) -> b3
    gemm_h16<<<gBig, 256, SM_H>>>(x16, win16, b2, b3, P0,
                                  BATCH, UNITS, INDIM, 1.0f, b_in,
                                  nullptr, 0.0f, bs[0], nullptr, 0.0f);

    float* RU[4] = {b2, b0, b2, nullptr};   // Ru_l fp32
    unsigned short* P[2] = {P0, P1};
    int sp = 0;   // P[sp] holds current layer's Ru fp16

    for (int l = 0; l < 3; ++l) {
        const float* W = Ws[l];
        unsigned short* Pc = P[sp];
        unsigned short* Po = P[sp ^ 1];

        weight_prep<<<tgrid, tblk>>>(w16, t16, W, UNITS);
        // K = W^T W  (fp16, fp32 out; error enters Minv scaled by a/c ~ 1e-3)
        gemm_h16<<<gSmall, 256, SM_H>>>(t16, t16, s1, nullptr, nullptr,
                                        UNITS, UNITS, UNITS, 1.0f, nullptr,
                                        nullptr, 0.0f, nullptr, nullptr, 0.0f);
        // mi16 = fp16(1024 * Minv) = (1024/c)I - (1024 a/c)K
        scale_diag16<<<sdBlocks, 256>>>(mi16, s1, -1024.0f * ACONST / CCONST,
                                        1024.0f / CCONST, UNITS);

        // r = dt*Ru@W + Rv  (B = W^T) -> fp16 Po
        gemm_h16<<<gBig, 256, SM_H>>>(Pc, t16, nullptr, nullptr, Po,
                                      BATCH, UNITS, UNITS, DT, nullptr,
                                      b3, 1.0f, nullptr, nullptr, 0.0f);
        // V = r @ (1024*Minv) / 1024 -> fp32 b1 (l<2) + fp16 Pc
        gemm_h16<<<gBig, 256, SM_H>>>(Po, mi16, (l < 2) ? b1 : nullptr, nullptr, Pc,
                                      BATCH, UNITS, UNITS, 1.0f / 1024.0f, nullptr,
                                      nullptr, 0.0f, nullptr, nullptr, 0.0f);
        // u_out = dt*V@W^T - Ru
        if (l < 2) {
            gemm_h16<<<gBig, 256, SM_H>>>(Pc, w16, RU[l + 1], b3, Po,
                                          BATCH, UNITS, UNITS, DT, nullptr,
                                          RU[l], -1.0f, bs[l + 1], b1, -1.0f);
        } else {
            gemm_h16<<<gBig, 256, SM_H>>>(Pc, w16, nullptr, nullptr, Po,
                                          BATCH, UNITS, UNITS, DT, nullptr,
                                          RU[l], -1.0f, nullptr, nullptr, 0.0f);
        }
        sp ^= 1;
    }

    // logits = u @ W_out^T + b_out -> out ; softmax
    gemm_h16<<<gOut, 256, SM_H>>>(P[sp], wo16, out, nullptr, nullptr,
                                  BATCH, OUTDIM, UNITS, 1.0f, b_out,
                                  nullptr, 0.0f, nullptr, nullptr, 0.0f);
    softmax_rows<<<BATCH, 256>>>(out, OUTDIM);
}